// round 5
// baseline (speedup 1.0000x reference)
#include <cuda_runtime.h>
#include <math.h>
#include <stdint.h>

#define NQ    20
#define NL    4
#define BATCH 16
#define DIM   (1 << NQ)
#define TOTAL (BATCH * DIM)

#define CB      8                      // batches per chunk (hot set = 2*CB*4MB = 64MB < L2)
#define NCHUNK  (BATCH / CB)

// Per-chunk scratch ping-pong buffers (reused across chunks -> L2 stays hot)
__device__ float  g_bufA[CB * DIM];
__device__ float  g_bufB[CB * DIM];
__device__ float2 g_rf[NL * NQ];   // .x = ratio (|r|<=1), .y = form (0 or 1)
__device__ float  g_absC;          // |product of per-gate scales|

// ---------------------------------------------------------------------------
// Fast-Givens precompute.
//   form0 (|c|>=|s|): M = c*[[1,-t],[t,1]], t=s/c
//   form1 (|s|> |c|): M = s*[[u,-1],[1,u]], u=c/s
// ---------------------------------------------------------------------------
__global__ void sincos_kernel(const float* __restrict__ theta) {
    __shared__ float sc[NL * NQ];
    int i = threadIdx.x;
    if (i < NL * NQ) {
        float t = 0.5f * theta[i];
        float c = cosf(t), s = sinf(t);
        bool form = fabsf(s) > fabsf(c);
        g_rf[i] = make_float2(form ? (c / s) : (s / c), form ? 1.0f : 0.0f);
        sc[i] = form ? s : c;
    }
    __syncthreads();
    if (i == 0) {
        float p = 1.0f;
        for (int k = 0; k < NL * NQ; k++) p *= sc[k];
        g_absC = fabsf(p);
    }
}

// ---------------------------------------------------------------------------
// Fast-Givens butterflies (1 FFMA per element per stage).
// ---------------------------------------------------------------------------
__device__ __forceinline__ float xsign(float v, uint32_t sg) {
    return __uint_as_float(__float_as_uint(v) ^ sg);
}

__device__ __forceinline__ void stage_reg_fg(float e[32], int m, float2 rf) {
    float r = rf.x;
    if (rf.y == 0.0f) {
#pragma unroll
        for (int j = 0; j < 32; j++)
            if ((j & m) == 0) {
                float a = e[j], b = e[j | m];
                e[j]     = fmaf(-r, b, a);
                e[j | m] = fmaf( r, a, b);
            }
    } else {
#pragma unroll
        for (int j = 0; j < 32; j++)
            if ((j & m) == 0) {
                float a = e[j], b = e[j | m];
                e[j]     = fmaf(r, a, -b);
                e[j | m] = fmaf(r, b,  a);
            }
    }
}

__device__ __forceinline__ void stage_xlane_fg(float e[32], int kbit, float2 rf, int lane) {
    int bit = (lane >> kbit) & 1;
    if (rf.y == 0.0f) {
        float rs = bit ? rf.x : -rf.x;
#pragma unroll
        for (int j = 0; j < 32; j++) {
            float o = __shfl_xor_sync(0xffffffffu, e[j], 1 << kbit);
            e[j] = fmaf(rs, o, e[j]);
        }
    } else {
        float r = rf.x;
        uint32_t sg = bit ? 0u : 0x80000000u;
#pragma unroll
        for (int j = 0; j < 32; j++) {
            float o = __shfl_xor_sync(0xffffffffu, e[j], 1 << kbit);
            e[j] = fmaf(r, e[j], xsign(o, sg));
        }
    }
}

// gray decode (p such that p ^ (p>>1) = g)
__device__ __host__ __forceinline__ constexpr int gdec(int g) {
    int p = g;
    p ^= p >> 1; p ^= p >> 2; p ^= p >> 4; p ^= p >> 8; p ^= p >> 16;
    return p;
}

// ---------------------------------------------------------------------------
// HIGH kernel: qubits 0..4 (index bits 19:15). Register butterflies,
// coalesced, in-place capable. Pointers are pre-offset to the chunk.
// ---------------------------------------------------------------------------
__global__ void __launch_bounds__(512, 3) high_kernel(const float* __restrict__ in,
                                                      float* __restrict__ out,
                                                      int layer) {
    const int blk = blockIdx.x;   // CB*64 blocks: batch = blk>>6, window = blk&63
    const size_t off = ((size_t)(blk >> 6) << 20) + (size_t)(blk & 63) * 512 + threadIdx.x;

    float e[32];
    const float* p = in + off;
#pragma unroll
    for (int k = 0; k < 32; k++) e[k] = p[(size_t)k << 15];

    const float2* rf = g_rf + layer * NQ;
    stage_reg_fg(e, 1,  rf[4]);
    stage_reg_fg(e, 2,  rf[3]);
    stage_reg_fg(e, 4,  rf[2]);
    stage_reg_fg(e, 8,  rf[1]);
    stage_reg_fg(e, 16, rf[0]);

    float* q = out + off;
#pragma unroll
    for (int k = 0; k < 32; k++) q[(size_t)k << 15] = e[k];
}

// ---------------------------------------------------------------------------
// LOW kernel: qubits 5..19 inside contiguous 32768-float tiles.
// 1024 threads, 32 regs/thread. Phase1: 5 shuffle + 5 reg stages; smem
// transpose; Phase2: 5 reg stages. Store folds the CNOT-chain permutation
// (gray-decode scatter, one 128B line per warp); FINAL applies |C|*|.|.
// ---------------------------------------------------------------------------
template <bool FINAL>
__global__ void __launch_bounds__(1024, 1) low_kernel(const float* __restrict__ in,
                                                      float* __restrict__ out,
                                                      int layer) {
    extern __shared__ float sm[];          // 32768 floats = 128 KB
    const int t = threadIdx.x & 31;
    const int w = threadIdx.x >> 5;
    const size_t tbase = (size_t)blockIdx.x << 15;   // grid = CB*32 tiles

    float e[32];
    const float* p = in + tbase;
#pragma unroll
    for (int j = 0; j < 32; j++) e[j] = p[j * 1024 + w * 32 + t];

    const float2* rf = g_rf + layer * NQ;
    stage_xlane_fg(e, 0, rf[19], t);
    stage_xlane_fg(e, 1, rf[18], t);
    stage_xlane_fg(e, 2, rf[17], t);
    stage_xlane_fg(e, 3, rf[16], t);
    stage_xlane_fg(e, 4, rf[15], t);
    stage_reg_fg(e, 1,  rf[9]);
    stage_reg_fg(e, 2,  rf[8]);
    stage_reg_fg(e, 4,  rf[7]);
    stage_reg_fg(e, 8,  rf[6]);
    stage_reg_fg(e, 16, rf[5]);

#pragma unroll
    for (int j = 0; j < 32; j++) sm[j * 1024 + w * 32 + t] = e[j];
    __syncthreads();
#pragma unroll
    for (int j = 0; j < 32; j++) e[j] = sm[w * 1024 + j * 32 + t];

    stage_reg_fg(e, 1,  rf[14]);
    stage_reg_fg(e, 2,  rf[13]);
    stage_reg_fg(e, 4,  rf[12]);
    stage_reg_fg(e, 8,  rf[11]);
    stage_reg_fg(e, 16, rf[10]);

    const int    tile20 = (int)(tbase & (DIM - 1));
    const size_t bbase  = tbase & ~((size_t)(DIM - 1));
    const int    pbase  = gdec(tile20 + (w << 10) + t);
    if (FINAL) {
        const float absC = g_absC;
#pragma unroll
        for (int j = 0; j < 32; j++) {
            int pp = pbase ^ gdec(j << 5);
            out[bbase + pp] = fabsf(e[j]) * absC;
        }
    } else {
#pragma unroll
        for (int j = 0; j < 32; j++) {
            int pp = pbase ^ gdec(j << 5);
            out[bbase + pp] = e[j];
        }
    }
}

// ---------------------------------------------------------------------------
extern "C" void kernel_launch(void* const* d_in, const int* in_sizes, int n_in,
                              void* d_out, int out_size) {
    const float* x     = (const float*)d_in[0];
    const float* theta = (const float*)d_in[1];
    float*       out   = (float*)d_out;

    float *bA = nullptr, *bB = nullptr;
    cudaGetSymbolAddress((void**)&bA, g_bufA);
    cudaGetSymbolAddress((void**)&bB, g_bufB);

    const int SMEM = 32768 * sizeof(float);
    cudaFuncSetAttribute(low_kernel<false>, cudaFuncAttributeMaxDynamicSharedMemorySize, SMEM);
    cudaFuncSetAttribute(low_kernel<true>,  cudaFuncAttributeMaxDynamicSharedMemorySize, SMEM);

    sincos_kernel<<<1, 128>>>(theta);

    const int GH = CB * 64;   // HIGH grid per chunk
    const int GL = CB * 32;   // LOW grid per chunk

    for (int c = 0; c < NCHUNK; c++) {
        const float* xc = x   + ((size_t)c * CB << 20);
        float*       oc = out + ((size_t)c * CB << 20);

        high_kernel<<<GH, 512>>>(xc, bA, 0);
        low_kernel<false><<<GL, 1024, SMEM>>>(bA, bB, 0);
        high_kernel<<<GH, 512>>>(bB, bB, 1);
        low_kernel<false><<<GL, 1024, SMEM>>>(bB, bA, 1);
        high_kernel<<<GH, 512>>>(bA, bA, 2);
        low_kernel<false><<<GL, 1024, SMEM>>>(bA, bB, 2);
        high_kernel<<<GH, 512>>>(bB, bB, 3);
        low_kernel<true><<<GL, 1024, SMEM>>>(bB, oc, 3);
    }
}